// round 3
// baseline (speedup 1.0000x reference)
#include <cuda_runtime.h>
#include <cuda_bf16.h>
#include <math.h>

// ---------------------------------------------------------------------------
// Problem constants
// ---------------------------------------------------------------------------
#define NB   128     // batch
#define NC   64      // channels / graph nodes
#define NT   500     // time
#define NF   16      // FEAT
#define NGC  32      // GC
#define NH   4       // heads
#define NROWS (NB*NC)  // 8192

// ---------------------------------------------------------------------------
// Device scratch (no allocations allowed)
// ---------------------------------------------------------------------------
__device__ float g_feats[NROWS * NF];
__device__ float g_M[NC * NC];
__device__ float g_h1[NROWS * NGC];
__device__ float g_h2[NROWS * NGC];
__device__ float g_sum1[NGC];
__device__ float g_sum2[NGC];

// ---------------------------------------------------------------------------
// f32x2 packed-math helpers (sm_103a: FFMA2 doubles fp32 FMA issue rate)
// ---------------------------------------------------------------------------
__device__ __forceinline__ unsigned long long pk2(float a, float b) {
    unsigned long long r;
    asm("mov.b64 %0, {%1, %2};" : "=l"(r) : "f"(a), "f"(b));
    return r;
}
__device__ __forceinline__ void upk2(unsigned long long v, float& a, float& b) {
    asm("mov.b64 {%0, %1}, %2;" : "=f"(a), "=f"(b) : "l"(v));
}
__device__ __forceinline__ void fma2(unsigned long long& d, unsigned long long a,
                                     unsigned long long b) {
    asm("fma.rn.f32x2 %0, %1, %2, %0;" : "+l"(d) : "l"(a), "l"(b));
}

__device__ __forceinline__ float eluf(float x) {
    return x > 0.f ? x : (__expf(x) - 1.f);
}

// ---------------------------------------------------------------------------
// Kernel A: fused EEG feature extractor.  One block per (b,c) sequence.
// conv1(K=25,pad=12)+BN+ELU -> dw(K=3)+BN+ELU -> sdw(K=3) -> pw(16x16)
// -> BN+ELU -> time-mean (AvgPool4 + adaptive pool == full mean, T%4==0).
// ---------------------------------------------------------------------------
// dyn smem layout (floats):
//   xs[560] | s1[16*504] | s2[16*504] | w1dup[800] | spwdup[512]
//   | dww[48] | sdws[48] | sc1,sh1,sc2,sh2,sc3,sh3 [96] | red[128]
#define FEAT_SMEM_FLOATS (560 + 8064 + 8064 + 800 + 512 + 48 + 48 + 96 + 128)
#define FEAT_SMEM_BYTES  (FEAT_SMEM_FLOATS * 4)

__global__ void feat_kernel(const float* __restrict__ x,
                            const float* __restrict__ c1w,
                            const float* __restrict__ bn1,
                            const float* __restrict__ dwwg,
                            const float* __restrict__ bn2,
                            const float* __restrict__ sdwg,
                            const float* __restrict__ spwg,
                            const float* __restrict__ bn3) {
    extern __shared__ float sm[];
    float* xs     = sm;                 // 560
    float* s1     = xs + 560;           // 16*504
    float* s2     = s1 + 8064;          // 16*504
    float* w1dup  = s2 + 8064;          // 400 float2
    float* spwdup = w1dup + 800;        // 256 float2
    float* dws    = spwdup + 512;       // 48
    float* sdws   = dws + 48;           // 48
    float* sc1    = sdws + 48;          // 16
    float* sh1    = sc1 + 16;
    float* sc2    = sh1 + 16;
    float* sh2    = sc2 + 16;
    float* sc3    = sh2 + 16;
    float* sh3    = sc3 + 16;
    float* red    = sh3 + 16;           // 8*16

    const int tid = threadIdx.x;
    const int seq = blockIdx.x;

    // --- load x (zero-padded halo), weights (duplicated for f32x2), BN ---
    {
        const float* xr = x + seq * NT;
        for (int i = tid; i < 560; i += 256) {
            float v = 0.f;
            if (i >= 12 && i < 512) v = xr[i - 12];
            xs[i] = v;
        }
        if (tid < 400) {
            float w = c1w[tid];
            ((float2*)w1dup)[tid] = make_float2(w, w);
        }
        { // 256 pointwise weights
            float w = spwg[tid];
            ((float2*)spwdup)[tid] = make_float2(w, w);
        }
        if (tid < 48) { dws[tid] = dwwg[tid]; sdws[tid] = sdwg[tid]; }
        if (tid < 16) {
            float s = bn1[tid] * rsqrtf(bn1[48 + tid] + 1e-5f);
            sc1[tid] = s; sh1[tid] = bn1[16 + tid] - bn1[32 + tid] * s;
            s = bn2[tid] * rsqrtf(bn2[48 + tid] + 1e-5f);
            sc2[tid] = s; sh2[tid] = bn2[16 + tid] - bn2[32 + tid] * s;
            s = bn3[tid] * rsqrtf(bn3[48 + tid] + 1e-5f);
            sc3[tid] = s; sh3[tid] = bn3[16 + tid] - bn3[32 + tid] * s;
        }
    }
    __syncthreads();

    const int t0 = tid;
    const int t1 = tid + 256;
    const bool v1 = (t1 < NT);

    // --- stage 1: conv1 (K=25) + BN + ELU, packed pair (t0,t1) ---
    {
        unsigned long long win[25];
#pragma unroll
        for (int k = 0; k < 25; k++) win[k] = pk2(xs[t0 + k], xs[t1 + k]);
        const unsigned long long* w1q = (const unsigned long long*)w1dup;
        for (int c = 0; c < 16; c++) {
            unsigned long long acc = 0ull;
#pragma unroll
            for (int k = 0; k < 25; k++) fma2(acc, win[k], w1q[c * 25 + k]);
            float a0, a1; upk2(acc, a0, a1);
            const float sc = sc1[c], sh = sh1[c];
            float* row = s1 + c * 504;
            row[1 + t0] = eluf(fmaf(a0, sc, sh));
            if (v1) row[1 + t1] = eluf(fmaf(a1, sc, sh));
        }
        if (tid < 16) { s1[tid * 504] = 0.f; s1[tid * 504 + 501] = 0.f; }
    }
    __syncthreads();

    // --- stage 2: depthwise conv (K=3) + BN + ELU ---
    for (int idx = tid; idx < 16 * NT; idx += 256) {
        const int c = idx / NT;
        const int t = idx - c * NT;
        const float* base = s1 + c * 504 + t;
        float v = dws[c * 3] * base[0] + dws[c * 3 + 1] * base[1] +
                  dws[c * 3 + 2] * base[2];
        s2[c * 504 + 1 + t] = eluf(fmaf(v, sc2[c], sh2[c]));
    }
    if (tid < 16) { s2[tid * 504] = 0.f; s2[tid * 504 + 501] = 0.f; }
    __syncthreads();

    // --- stage 3: sdw (K=3) -> pointwise 16x16 -> BN+ELU -> accumulate mean ---
    float acc[16];
#pragma unroll
    for (int f = 0; f < 16; f++) acc[f] = 0.f;
    {
        const int t1r = v1 ? t1 : 0;
        unsigned long long tmp[16];
#pragma unroll
        for (int c = 0; c < 16; c++) {
            const float* r = s2 + c * 504;
            const float w0 = sdws[c * 3], w1w = sdws[c * 3 + 1], w2 = sdws[c * 3 + 2];
            float u0 = w0 * r[t0] + w1w * r[t0 + 1] + w2 * r[t0 + 2];
            float u1 = w0 * r[t1r] + w1w * r[t1r + 1] + w2 * r[t1r + 2];
            tmp[c] = pk2(u0, u1);
        }
        const unsigned long long* spq = (const unsigned long long*)spwdup;
        for (int f = 0; f < 16; f++) {
            unsigned long long a = 0ull;
#pragma unroll
            for (int c = 0; c < 16; c++) fma2(a, tmp[c], spq[f * 16 + c]);
            float a0, a1; upk2(a, a0, a1);
            const float sc = sc3[f], sh = sh3[f];
            acc[f] += eluf(fmaf(a0, sc, sh));
            if (v1) acc[f] += eluf(fmaf(a1, sc, sh));
        }
    }

    // --- reduce over 256 threads, write feats ---
    {
        const int lane = tid & 31, wid = tid >> 5;
#pragma unroll
        for (int f = 0; f < 16; f++) {
            float v = acc[f];
            for (int o = 16; o; o >>= 1) v += __shfl_down_sync(0xffffffffu, v, o);
            if (lane == 0) red[wid * 16 + f] = v;
        }
        __syncthreads();
        if (tid < 16) {
            float s = 0.f;
            for (int w = 0; w < 8; w++) s += red[w * 16 + tid];
            g_feats[seq * 16 + tid] = s * (1.f / (float)NT);
        }
    }
}

// ---------------------------------------------------------------------------
// Kernel B: build multiplicity matrix M, zero SE accumulators.  One block.
// ---------------------------------------------------------------------------
__global__ void graph_kernel(const float* __restrict__ emb,
                             const int* __restrict__ eidx) {
    __shared__ float E[NC * NF];
    __shared__ float As[NC * 65];
    __shared__ float rs[NC];
    __shared__ float Ms[NC * NC];
    const int tid = threadIdx.x;

    for (int i = tid; i < NC * NF; i += 256) E[i] = emb[i];
    for (int i = tid; i < NC * NC; i += 256) Ms[i] = 0.f;
    if (tid < NGC) { g_sum1[tid] = 0.f; g_sum2[tid] = 0.f; }
    __syncthreads();

    for (int idx = tid; idx < NC * NC; idx += 256) {
        const int i = idx >> 6, j = idx & 63;
        float a = 0.f;
#pragma unroll
        for (int f = 0; f < NF; f++) a += E[i * NF + f] * E[j * NF + f];
        As[i * 65 + j] = fmaxf(a, 0.f);
    }
    __syncthreads();
    if (tid < NC) {
        float s = 0.f;
        for (int j = 0; j < NC; j++) s += As[tid * 65 + j];
        rs[tid] = s + 1e-6f;
    }
    __syncthreads();
    if (tid < 256) {
        const int s = eidx[tid], d = eidx[256 + tid];
        atomicAdd(&Ms[s * NC + d], 1.f);
    }
    __syncthreads();
    for (int idx = tid; idx < NC * NC; idx += 256) {
        const int i = idx >> 6, j = idx & 63;
        const float dyn = (As[i * 65 + j] / rs[i] > 0.1f) ? 1.f : 0.f;
        g_M[idx] = (i == j) ? 1.f : (Ms[idx] + dyn);
    }
}

// ---------------------------------------------------------------------------
// Kernel C: GAT layer (+BN +skip/residual +GELU +SE partial sums).
// One block per batch element.  LAYER==1: input g_feats, skip proj, out g_h1.
// LAYER==2: input g_h1 gated by SE1, residual, out g_h2.
// xl stored permuted as [j][f*4+h] so the hot aggregation loop is
// broadcast/conflict-free LDS and the head-mean is one float4 load.
// ---------------------------------------------------------------------------
#define GAT_SMEM_FLOATS(INF) (2112 + 8192 + (INF)*128 + 4160 + 256 + 256 + 136)
#define GAT_SMEM_BYTES(INF)  (GAT_SMEM_FLOATS(INF) * 4)

template <int INF, int LAYER>
__global__ void gat_kernel(const float* __restrict__ W,
                           const float* __restrict__ asrc,
                           const float* __restrict__ adst,
                           const float* __restrict__ bias,
                           const float* __restrict__ bnp,
                           const float* __restrict__ skipw,
                           const float* __restrict__ sew1,
                           const float* __restrict__ sew2) {
    extern __shared__ float sm[];
    float* Xs   = sm;                   // 64*33
    float* xlS  = Xs + 2112;            // 64*128
    float* Ws   = xlS + 8192;           // INF*128 (permuted)
    float* Ms   = Ws + INF * 128;       // 64*65 (reused as hs[64*33])
    float* ss   = Ms + 4160;            // 64*4
    float* dd   = ss + 256;             // 64*4
    float* bnsc = dd + 256;             // 32
    float* bnsh = bnsc + 32;            // 32
    float* gate = bnsh + 32;            // 32
    float* msm  = gate + 32;            // 32
    float* t8m  = msm + 32;             // 8

    const int tid = threadIdx.x;
    const int b   = blockIdx.x;
    const float* Xin = (LAYER == 1) ? g_feats : g_h1;

    if (tid < 32) {
        const float s = bnp[tid] * rsqrtf(bnp[96 + tid] + 1e-5f);
        bnsc[tid] = s; bnsh[tid] = bnp[32 + tid] - bnp[64 + tid] * s;
    }
    if (LAYER == 2) {
        if (tid < 32) msm[tid] = g_sum1[tid] * (1.f / (float)NROWS);
        __syncthreads();
        if (tid < 8) {
            float a = 0.f;
#pragma unroll
            for (int f = 0; f < 32; f++) a += msm[f] * sew1[tid * 32 + f];
            t8m[tid] = fmaxf(a, 0.f);
        }
        __syncthreads();
        if (tid < 32) {
            float a = 0.f;
#pragma unroll
            for (int k = 0; k < 8; k++) a += t8m[k] * sew2[tid * 8 + k];
            gate[tid] = 1.f / (1.f + __expf(-a));
        }
    }
    // load M (padded rows) and W (permuted col h*32+f -> f*4+h)
    for (int i = tid; i < NC * NC; i += 256)
        Ms[(i >> 6) * 65 + (i & 63)] = g_M[i];
    for (int i = tid; i < INF * 128; i += 256) {
        const int in = i >> 7, c = i & 127;
        Ws[in * 128 + ((c & 31) << 2) + (c >> 5)] = W[i];
    }
    __syncthreads();  // gate + Ws + Ms ready
    for (int i = tid; i < NC * INF; i += 256) {
        const int r = i / INF, f = i - r * INF;
        float v = Xin[(b * NC + r) * INF + f];
        if (LAYER == 2) v *= gate[f];
        Xs[r * 33 + f] = v;
    }
    __syncthreads();

    // xl = X @ W  (float4 over permuted cols)
    for (int qd = tid; qd < 2048; qd += 256) {
        const int j = qd >> 5;
        const int q0 = (qd & 31) << 2;
        float4 a = make_float4(0.f, 0.f, 0.f, 0.f);
#pragma unroll
        for (int in = 0; in < INF; in++) {
            const float xv = Xs[j * 33 + in];
            const float4 wv = *(const float4*)(Ws + in * 128 + q0);
            a.x = fmaf(xv, wv.x, a.x); a.y = fmaf(xv, wv.y, a.y);
            a.z = fmaf(xv, wv.z, a.z); a.w = fmaf(xv, wv.w, a.w);
        }
        *(float4*)(xlS + j * 128 + q0) = a;
    }
    __syncthreads();

    // s[j,h], d[j,h]
    {
        const int j = tid >> 2, h = tid & 3;
        float sv = 0.f, dv = 0.f;
#pragma unroll
        for (int f = 0; f < 32; f++) {
            const float xv = xlS[j * 128 + f * 4 + h];
            sv = fmaf(xv, asrc[h * 32 + f], sv);
            dv = fmaf(xv, adst[h * 32 + f], dv);
        }
        ss[j * 4 + h] = sv; dd[j * 4 + h] = dv;
    }
    __syncthreads();

    // attention: thread = (i,h)
    const int i = tid >> 2, h = tid & 3;
    const float di = dd[i * 4 + h];
    float mx = -1e30f;
    for (int j = 0; j < NC; j++) {
        const float Mij = Ms[i * 65 + j];
        float e = di + ss[j * 4 + h];
        e = (e >= 0.f) ? e : 0.2f * e;
        mx = (Mij > 0.f) ? fmaxf(mx, e) : mx;
    }
    float Z = 0.f;
    float acc[32];
#pragma unroll
    for (int f = 0; f < 32; f++) acc[f] = 0.f;
    for (int j = 0; j < NC; j++) {
        const float Mij = Ms[i * 65 + j];
        float e = di + ss[j * 4 + h];
        e = (e >= 0.f) ? e : 0.2f * e;
        const float w = Mij * __expf(e - mx);
        Z += w;
        const float* xr = xlS + j * 128 + h;
#pragma unroll
        for (int f = 0; f < 32; f++) acc[f] = fmaf(w, xr[f * 4], acc[f]);
    }
    const float invZ = 1.f / Z;
    __syncthreads();  // all xlS reads complete
#pragma unroll
    for (int f = 0; f < 32; f++) xlS[i * 128 + f * 4 + h] = acc[f] * invZ;
    __syncthreads();

    // epilogue: head mean + bias + BN + skip/residual + exact GELU
    float* hs = Ms;  // reuse
    for (int idx = tid; idx < NC * 32; idx += 256) {
        const int r = idx >> 5, f = idx & 31;
        const float4 v = *(const float4*)(xlS + r * 128 + f * 4);
        float o = (v.x + v.y + v.z + v.w) * 0.25f + bias[f];
        o = fmaf(o, bnsc[f], bnsh[f]);
        float res;
        if (LAYER == 1) {
            res = 0.f;
#pragma unroll
            for (int in = 0; in < 16; in++)
                res = fmaf(Xs[r * 33 + in], skipw[f * 16 + in], res);
        } else {
            res = Xs[r * 33 + f];
        }
        o += res;
        const float gl = 0.5f * o * (1.f + erff(o * 0.70710678118f));
        float* Hout = (LAYER == 1) ? g_h1 : g_h2;
        Hout[(b * NC + r) * 32 + f] = gl;
        hs[r * 33 + f] = gl;
    }
    __syncthreads();
    if (tid < 32) {
        float s = 0.f;
        for (int r = 0; r < NC; r++) s += hs[r * 33 + tid];
        float* so = (LAYER == 1) ? g_sum1 : g_sum2;
        atomicAdd(&so[tid], s);
    }
}

// ---------------------------------------------------------------------------
// Kernel D: SE2 gate + node mean-pool + classifier.  One block per batch.
// ---------------------------------------------------------------------------
__global__ void final_kernel(const float* __restrict__ sew1,
                             const float* __restrict__ sew2,
                             const float* __restrict__ clfw,
                             const float* __restrict__ clfb,
                             float* __restrict__ out) {
    __shared__ float rows[NC * 33];
    __shared__ float msm[32], t8m[8], gate[32], pooled[32];
    const int tid = threadIdx.x;
    const int b   = blockIdx.x;

    if (tid < 32) msm[tid] = g_sum2[tid] * (1.f / (float)NROWS);
    __syncthreads();
    if (tid < 8) {
        float a = 0.f;
#pragma unroll
        for (int f = 0; f < 32; f++) a += msm[f] * sew1[tid * 32 + f];
        t8m[tid] = fmaxf(a, 0.f);
    }
    __syncthreads();
    if (tid < 32) {
        float a = 0.f;
#pragma unroll
        for (int k = 0; k < 8; k++) a += t8m[k] * sew2[tid * 8 + k];
        gate[tid] = 1.f / (1.f + __expf(-a));
    }
    {
        const float* hp = g_h2 + (b * NC + tid) * 32;
#pragma unroll
        for (int f = 0; f < 32; f++) rows[tid * 33 + f] = hp[f];
    }
    __syncthreads();
    if (tid < 32) {
        float s = 0.f;
        for (int c = 0; c < NC; c++) s += rows[c * 33 + tid];
        pooled[tid] = s * (1.f / (float)NC) * gate[tid];
    }
    __syncthreads();
    if (tid < 2) {
        float a = clfb[tid];
#pragma unroll
        for (int f = 0; f < 32; f++) a += pooled[f] * clfw[tid * 32 + f];
        out[b * 2 + tid] = a;
    }
}

// ---------------------------------------------------------------------------
// Launch
// ---------------------------------------------------------------------------
extern "C" void kernel_launch(void* const* d_in, const int* in_sizes, int n_in,
                              void* d_out, int out_size) {
    const float* x      = (const float*)d_in[0];
    const int*   eidx   = (const int*)  d_in[1];
    const float* c1w    = (const float*)d_in[2];
    const float* bn_c1  = (const float*)d_in[3];
    const float* dw_w   = (const float*)d_in[4];
    const float* bn_c2  = (const float*)d_in[5];
    const float* sdw_w  = (const float*)d_in[6];
    const float* spw_w  = (const float*)d_in[7];
    const float* bn_c3  = (const float*)d_in[8];
    const float* embed  = (const float*)d_in[9];
    const float* g1_w   = (const float*)d_in[10];
    const float* g1_as  = (const float*)d_in[11];
    const float* g1_ad  = (const float*)d_in[12];
    const float* g1_b   = (const float*)d_in[13];
    const float* bn_g1  = (const float*)d_in[14];
    const float* skip1  = (const float*)d_in[15];
    const float* se1w1  = (const float*)d_in[16];
    const float* se1w2  = (const float*)d_in[17];
    const float* g2_w   = (const float*)d_in[18];
    const float* g2_as  = (const float*)d_in[19];
    const float* g2_ad  = (const float*)d_in[20];
    const float* g2_b   = (const float*)d_in[21];
    const float* bn_g2  = (const float*)d_in[22];
    const float* se2w1  = (const float*)d_in[23];
    const float* se2w2  = (const float*)d_in[24];
    const float* clf_w  = (const float*)d_in[25];
    const float* clf_b  = (const float*)d_in[26];
    float* out = (float*)d_out;

    cudaFuncSetAttribute(feat_kernel, cudaFuncAttributeMaxDynamicSharedMemorySize,
                         FEAT_SMEM_BYTES);
    cudaFuncSetAttribute(gat_kernel<16, 1>,
                         cudaFuncAttributeMaxDynamicSharedMemorySize,
                         GAT_SMEM_BYTES(16));
    cudaFuncSetAttribute(gat_kernel<32, 2>,
                         cudaFuncAttributeMaxDynamicSharedMemorySize,
                         GAT_SMEM_BYTES(32));

    feat_kernel<<<NROWS, 256, FEAT_SMEM_BYTES>>>(x, c1w, bn_c1, dw_w, bn_c2,
                                                 sdw_w, spw_w, bn_c3);
    graph_kernel<<<1, 256>>>(embed, eidx);
    gat_kernel<16, 1><<<NB, 256, GAT_SMEM_BYTES(16)>>>(
        g1_w, g1_as, g1_ad, g1_b, bn_g1, skip1, nullptr, nullptr);
    gat_kernel<32, 2><<<NB, 256, GAT_SMEM_BYTES(32)>>>(
        g2_w, g2_as, g2_ad, g2_b, bn_g2, nullptr, se1w1, se1w2);
    final_kernel<<<NB, 64>>>(se2w1, se2w2, clf_w, clf_b, out);
}

// round 4
// speedup vs baseline: 1.0904x; 1.0904x over previous
#include <cuda_runtime.h>
#include <cuda_fp16.h>
#include <math.h>

// ---------------------------------------------------------------------------
// Problem constants
// ---------------------------------------------------------------------------
#define NB   128
#define NC   64
#define NT   500
#define NF   16
#define NGC  32
#define NH   4
#define NROWS (NB*NC)   // 8192

// ---------------------------------------------------------------------------
// Device scratch
// ---------------------------------------------------------------------------
__device__ float g_feats[NROWS * NF];
__device__ float g_M[NC * NC];
__device__ float g_h1[NROWS * NGC];
__device__ float g_h2[NROWS * NGC];
__device__ float g_sum1[NGC];
__device__ float g_sum2[NGC];
__device__ float g_headout[NB * NH * NC * NGC];   // [b][h][i][f]  4MB

// ---------------------------------------------------------------------------
// f32x2 packed helpers
// ---------------------------------------------------------------------------
__device__ __forceinline__ unsigned long long pk2(float a, float b) {
    unsigned long long r;
    asm("mov.b64 %0, {%1, %2};" : "=l"(r) : "f"(a), "f"(b));
    return r;
}
__device__ __forceinline__ void upk2(unsigned long long v, float& a, float& b) {
    asm("mov.b64 {%0, %1}, %2;" : "=f"(a), "=f"(b) : "l"(v));
}
__device__ __forceinline__ void fma2(unsigned long long& d, unsigned long long a,
                                     unsigned long long b) {
    asm("fma.rn.f32x2 %0, %1, %2, %0;" : "+l"(d) : "l"(a), "l"(b));
}
__device__ __forceinline__ float eluf(float x) {
    return x > 0.f ? x : (__expf(x) - 1.f);
}

// ---------------------------------------------------------------------------
// Kernel A: fused feature extractor.  One block per (b,c) sequence.
// Redesigned for occupancy: k-outer conv1 (acc regs instead of window regs),
// fp16 stage-2 buffer.  smem 57152B -> 4 CTAs/SM;  regs capped at 64.
// byte layout:
//   0      xs      560 f
//   2240   s1      8064 f          (16 rows x 504, data at [1..500])
//   34496  s2h     8064 half
//   50624  w1dup   800 f  (400 float2)
//   53824  spwdup  512 f  (256 float2)
//   55872  dws     48 f
//   56064  sdws    48 f
//   56256  bn      96 f   (sc1,sh1,sc2,sh2,sc3,sh3)
//   56640  red     128 f
// ---------------------------------------------------------------------------
#define FEAT_SMEM_BYTES 57152

__global__ __launch_bounds__(256, 4)
void feat_kernel(const float* __restrict__ x,
                 const float* __restrict__ c1w,
                 const float* __restrict__ bn1,
                 const float* __restrict__ dwwg,
                 const float* __restrict__ bn2,
                 const float* __restrict__ sdwg,
                 const float* __restrict__ spwg,
                 const float* __restrict__ bn3) {
    extern __shared__ char smraw[];
    float*  xs     = (float*)(smraw);
    float*  s1     = (float*)(smraw + 2240);
    __half* s2h    = (__half*)(smraw + 34496);
    float*  w1dup  = (float*)(smraw + 50624);
    float*  spwdup = (float*)(smraw + 53824);
    float*  dws    = (float*)(smraw + 55872);
    float*  sdws   = (float*)(smraw + 56064);
    float*  sc1    = (float*)(smraw + 56256);
    float*  sh1 = sc1 + 16; float* sc2 = sc1 + 32; float* sh2 = sc1 + 48;
    float*  sc3 = sc1 + 64; float* sh3 = sc1 + 80;
    float*  red    = (float*)(smraw + 56640);

    const int tid = threadIdx.x;
    const int seq = blockIdx.x;

    {
        const float* xr = x + seq * NT;
        for (int i = tid; i < 560; i += 256) {
            float v = 0.f;
            if (i >= 12 && i < 512) v = xr[i - 12];
            xs[i] = v;
        }
        if (tid < 400) {
            float w = c1w[tid];
            ((float2*)w1dup)[tid] = make_float2(w, w);
        }
        {
            float w = spwg[tid];
            ((float2*)spwdup)[tid] = make_float2(w, w);
        }
        if (tid < 48) { dws[tid] = dwwg[tid]; sdws[tid] = sdwg[tid]; }
        if (tid < 16) {
            float s = bn1[tid] * rsqrtf(bn1[48 + tid] + 1e-5f);
            sc1[tid] = s; sh1[tid] = bn1[16 + tid] - bn1[32 + tid] * s;
            s = bn2[tid] * rsqrtf(bn2[48 + tid] + 1e-5f);
            sc2[tid] = s; sh2[tid] = bn2[16 + tid] - bn2[32 + tid] * s;
            s = bn3[tid] * rsqrtf(bn3[48 + tid] + 1e-5f);
            sc3[tid] = s; sh3[tid] = bn3[16 + tid] - bn3[32 + tid] * s;
        }
    }
    __syncthreads();

    const int t0 = tid;
    const int t1 = tid + 256;
    const bool v1 = (t1 < NT);

    // --- stage 1: conv1 (K=25) + BN + ELU, k-outer with packed accumulators
    {
        unsigned long long acc1[16];
#pragma unroll
        for (int c = 0; c < 16; c++) acc1[c] = 0ull;
        const unsigned long long* w1q = (const unsigned long long*)w1dup;
#pragma unroll 5
        for (int k = 0; k < 25; k++) {
            const unsigned long long xv = pk2(xs[t0 + k], xs[t1 + k]);
#pragma unroll
            for (int c = 0; c < 16; c++) fma2(acc1[c], xv, w1q[c * 25 + k]);
        }
#pragma unroll
        for (int c = 0; c < 16; c++) {
            float a0, a1; upk2(acc1[c], a0, a1);
            const float sc = sc1[c], sh = sh1[c];
            float* row = s1 + c * 504;
            row[1 + t0] = eluf(fmaf(a0, sc, sh));
            if (v1) row[1 + t1] = eluf(fmaf(a1, sc, sh));
        }
        if (tid < 16) { s1[tid * 504] = 0.f; s1[tid * 504 + 501] = 0.f; }
    }
    __syncthreads();

    // --- stage 2: depthwise conv (K=3) + BN + ELU -> fp16 buffer
#pragma unroll
    for (int c = 0; c < 16; c++) {
        const float* r = s1 + c * 504;
        const float w0 = dws[c * 3], wA = dws[c * 3 + 1], w2 = dws[c * 3 + 2];
        const float sc = sc2[c], sh = sh2[c];
        float v0 = w0 * r[t0] + wA * r[t0 + 1] + w2 * r[t0 + 2];
        s2h[c * 504 + 1 + t0] = __float2half(eluf(fmaf(v0, sc, sh)));
        if (v1) {
            float u = w0 * r[t1] + wA * r[t1 + 1] + w2 * r[t1 + 2];
            s2h[c * 504 + 1 + t1] = __float2half(eluf(fmaf(u, sc, sh)));
        }
    }
    if (tid < 16) {
        s2h[tid * 504] = __float2half(0.f);
        s2h[tid * 504 + 501] = __float2half(0.f);
    }
    __syncthreads();

    // --- stage 3: sdw (K=3) -> pointwise 16x16 (packed) -> BN+ELU -> mean
    float means[16];
    {
        const int t1r = v1 ? t1 : 0;
        unsigned long long tmp[16];
#pragma unroll
        for (int c = 0; c < 16; c++) {
            const __half* r = s2h + c * 504;
            const float w0 = sdws[c * 3], wA = sdws[c * 3 + 1], w2 = sdws[c * 3 + 2];
            float a0 = w0 * __half2float(r[t0]) + wA * __half2float(r[t0 + 1]) +
                       w2 * __half2float(r[t0 + 2]);
            float a1 = w0 * __half2float(r[t1r]) + wA * __half2float(r[t1r + 1]) +
                       w2 * __half2float(r[t1r + 2]);
            tmp[c] = pk2(a0, a1);
        }
        const unsigned long long* spq = (const unsigned long long*)spwdup;
#pragma unroll
        for (int f = 0; f < 16; f++) {
            unsigned long long a = 0ull;
#pragma unroll
            for (int c = 0; c < 16; c++) fma2(a, tmp[c], spq[f * 16 + c]);
            float a0, a1; upk2(a, a0, a1);
            const float sc = sc3[f], sh = sh3[f];
            float e0 = eluf(fmaf(a0, sc, sh));
            float e1 = eluf(fmaf(a1, sc, sh));
            means[f] = e0 + (v1 ? e1 : 0.f);
        }
    }

    {
        const int lane = tid & 31, wid = tid >> 5;
#pragma unroll
        for (int f = 0; f < 16; f++) {
            float v = means[f];
            for (int o = 16; o; o >>= 1) v += __shfl_down_sync(0xffffffffu, v, o);
            if (lane == 0) red[wid * 16 + f] = v;
        }
        __syncthreads();
        if (tid < 16) {
            float s = 0.f;
            for (int w = 0; w < 8; w++) s += red[w * 16 + tid];
            g_feats[seq * 16 + tid] = s * (1.f / (float)NT);
        }
    }
}

// ---------------------------------------------------------------------------
// Kernel B: build multiplicity matrix M, zero SE accumulators.  One block.
// ---------------------------------------------------------------------------
__global__ void graph_kernel(const float* __restrict__ emb,
                             const int* __restrict__ eidx) {
    __shared__ float E[NC * NF];
    __shared__ float As[NC * 65];
    __shared__ float rs[NC];
    __shared__ float Ms[NC * NC];
    const int tid = threadIdx.x;

    for (int i = tid; i < NC * NF; i += 256) E[i] = emb[i];
    for (int i = tid; i < NC * NC; i += 256) Ms[i] = 0.f;
    if (tid < NGC) { g_sum1[tid] = 0.f; g_sum2[tid] = 0.f; }
    __syncthreads();

    for (int idx = tid; idx < NC * NC; idx += 256) {
        const int i = idx >> 6, j = idx & 63;
        float a = 0.f;
#pragma unroll
        for (int f = 0; f < NF; f++) a += E[i * NF + f] * E[j * NF + f];
        As[i * 65 + j] = fmaxf(a, 0.f);
    }
    __syncthreads();
    if (tid < NC) {
        float s = 0.f;
        for (int j = 0; j < NC; j++) s += As[tid * 65 + j];
        rs[tid] = s + 1e-6f;
    }
    __syncthreads();
    if (tid < 256) {
        const int s = eidx[tid], d = eidx[256 + tid];
        atomicAdd(&Ms[s * NC + d], 1.f);
    }
    __syncthreads();
    for (int idx = tid; idx < NC * NC; idx += 256) {
        const int i = idx >> 6, j = idx & 63;
        const float dyn = (As[i * 65 + j] / rs[i] > 0.1f) ? 1.f : 0.f;
        g_M[idx] = (i == j) ? 1.f : (Ms[idx] + dyn);
    }
}

// ---------------------------------------------------------------------------
// Kernel C: per-(batch,head) GAT attention.  512 blocks -> real occupancy.
// Writes per-head results to g_headout[b][h][i][f].
// ---------------------------------------------------------------------------
template <int INF, int LAYER>
__global__ __launch_bounds__(256)
void gat_head_kernel(const float* __restrict__ W,
                     const float* __restrict__ asrc,
                     const float* __restrict__ adst,
                     const float* __restrict__ sew1,
                     const float* __restrict__ sew2) {
    __shared__ float Xs[NC * (INF + 1)];
    __shared__ float Wh[INF * 33];
    __shared__ float xl[NC * 33];
    __shared__ float ss[NC];
    __shared__ float dd[NC];
    __shared__ float Ms[NC * 65];
    __shared__ float gate[32], msm[32], t8m[8];

    const int tid = threadIdx.x;
    const int h = blockIdx.x & 3;
    const int b = blockIdx.x >> 2;
    const float* Xin = (LAYER == 1) ? g_feats : g_h1;

    if (LAYER == 2) {
        if (tid < 32) msm[tid] = g_sum1[tid] * (1.f / (float)NROWS);
        __syncthreads();
        if (tid < 8) {
            float a = 0.f;
#pragma unroll
            for (int f = 0; f < 32; f++) a += msm[f] * sew1[tid * 32 + f];
            t8m[tid] = fmaxf(a, 0.f);
        }
        __syncthreads();
        if (tid < 32) {
            float a = 0.f;
#pragma unroll
            for (int k = 0; k < 8; k++) a += t8m[k] * sew2[tid * 8 + k];
            gate[tid] = 1.f / (1.f + __expf(-a));
        }
        __syncthreads();
    }

    for (int i = tid; i < NC * NC; i += 256)
        Ms[(i >> 6) * 65 + (i & 63)] = g_M[i];
    for (int i = tid; i < INF * 32; i += 256) {
        const int in = i >> 5, f = i & 31;
        Wh[in * 33 + f] = W[in * 128 + h * 32 + f];
    }
    for (int i = tid; i < NC * INF; i += 256) {
        const int r = i / INF, f = i - r * INF;
        float v = Xin[(b * NC + r) * INF + f];
        if (LAYER == 2) v *= gate[f];
        Xs[r * (INF + 1) + f] = v;
    }
    __syncthreads();

    // xl[j][f] = sum_in Xs[j][in] * Wh[in][f]
    for (int idx = tid; idx < NC * 32; idx += 256) {
        const int j = idx >> 5, f = idx & 31;
        float a = 0.f;
#pragma unroll
        for (int in = 0; in < INF; in++)
            a = fmaf(Xs[j * (INF + 1) + in], Wh[in * 33 + f], a);
        xl[j * 33 + f] = a;
    }
    __syncthreads();

    if (tid < 128) {
        const int node = tid & 63, which = tid >> 6;
        const float* av = which ? adst : asrc;
        float a = 0.f;
#pragma unroll
        for (int f = 0; f < 32; f++)
            a = fmaf(xl[node * 33 + f], av[h * 32 + f], a);
        if (which) dd[node] = a; else ss[node] = a;
    }
    __syncthreads();

    // attention: thread = (i, q); q covers 8 features
    const int i = tid >> 2, q = tid & 3;
    const float di = dd[i];
    float mx = -1e30f;
    for (int j = 0; j < NC; j++) {
        const float Mij = Ms[i * 65 + j];
        float e = di + ss[j];
        e = (e >= 0.f) ? e : 0.2f * e;
        mx = (Mij > 0.f) ? fmaxf(mx, e) : mx;
    }
    float Z = 0.f;
    float acc[8];
#pragma unroll
    for (int f = 0; f < 8; f++) acc[f] = 0.f;
    const float* xr = xl + q * 8;
    for (int j = 0; j < NC; j++) {
        const float Mij = Ms[i * 65 + j];
        float e = di + ss[j];
        e = (e >= 0.f) ? e : 0.2f * e;
        const float w = Mij * __expf(e - mx);
        Z += w;
        const float* row = xr + j * 33;
#pragma unroll
        for (int f = 0; f < 8; f++) acc[f] = fmaf(w, row[f], acc[f]);
    }
    const float invZ = 1.f / Z;
    float* outp = g_headout + ((b * 4 + h) * NC + i) * 32 + q * 8;
#pragma unroll
    for (int f = 0; f < 8; f++) outp[f] = acc[f] * invZ;
}

// ---------------------------------------------------------------------------
// Kernel D: GAT epilogue: head mean + bias + BN + skip/residual + GELU,
// write h, accumulate SE sums.  1024 blocks x 256 thr (8 rows x 32 f each).
// ---------------------------------------------------------------------------
template <int LAYER>
__global__ __launch_bounds__(256)
void gat_epi_kernel(const float* __restrict__ bias,
                    const float* __restrict__ bnp,
                    const float* __restrict__ skipw,
                    const float* __restrict__ sew1,
                    const float* __restrict__ sew2) {
    __shared__ float bnsc[32], bnsh[32], bs[32];
    __shared__ float sk[512];               // layer1: skipw transposed [in][f]
    __shared__ float gate[32], msm[32], t8m[8];
    __shared__ float red[8 * 32];

    const int tid = threadIdx.x;
    if (tid < 32) {
        const float s = bnp[tid] * rsqrtf(bnp[96 + tid] + 1e-5f);
        bnsc[tid] = s; bnsh[tid] = bnp[32 + tid] - bnp[64 + tid] * s;
        bs[tid] = bias[tid];
    }
    if (LAYER == 1) {
        for (int i = tid; i < 512; i += 256)
            sk[i] = skipw[(i & 31) * 16 + (i >> 5)];   // sk[in*32+f]
    } else {
        if (tid < 32) msm[tid] = g_sum1[tid] * (1.f / (float)NROWS);
        __syncthreads();
        if (tid < 8) {
            float a = 0.f;
#pragma unroll
            for (int f = 0; f < 32; f++) a += msm[f] * sew1[tid * 32 + f];
            t8m[tid] = fmaxf(a, 0.f);
        }
        __syncthreads();
        if (tid < 32) {
            float a = 0.f;
#pragma unroll
            for (int k = 0; k < 8; k++) a += t8m[k] * sew2[tid * 8 + k];
            gate[tid] = 1.f / (1.f + __expf(-a));
        }
    }
    __syncthreads();

    const int w = tid >> 5, f = tid & 31;
    const int row = blockIdx.x * 8 + w;
    const int b = row >> 6, i = row & 63;

    float o = 0.f;
#pragma unroll
    for (int h = 0; h < 4; h++)
        o += g_headout[((b * 4 + h) * NC + i) * 32 + f];
    o = o * 0.25f + bs[f];
    o = fmaf(o, bnsc[f], bnsh[f]);

    float res;
    if (LAYER == 1) {
        const float* xr = g_feats + row * 16;
        res = 0.f;
#pragma unroll
        for (int in = 0; in < 16; in++)
            res = fmaf(__ldg(xr + in), sk[in * 32 + f], res);
    } else {
        res = gate[f] * g_h1[row * 32 + f];
    }
    o += res;
    const float gl = 0.5f * o * (1.f + erff(o * 0.70710678118f));
    ((LAYER == 1) ? g_h1 : g_h2)[row * 32 + f] = gl;

    red[w * 32 + f] = gl;
    __syncthreads();
    if (tid < 32) {
        float s = 0.f;
#pragma unroll
        for (int r = 0; r < 8; r++) s += red[r * 32 + tid];
        atomicAdd((LAYER == 1) ? &g_sum1[tid] : &g_sum2[tid], s);
    }
}

// ---------------------------------------------------------------------------
// Kernel E: SE2 gate + node mean-pool + classifier.  One block per batch.
// ---------------------------------------------------------------------------
__global__ void final_kernel(const float* __restrict__ sew1,
                             const float* __restrict__ sew2,
                             const float* __restrict__ clfw,
                             const float* __restrict__ clfb,
                             float* __restrict__ out) {
    __shared__ float rows[NC * 33];
    __shared__ float msm[32], t8m[8], gate[32], pooled[32];
    const int tid = threadIdx.x;
    const int b   = blockIdx.x;

    if (tid < 32) msm[tid] = g_sum2[tid] * (1.f / (float)NROWS);
    __syncthreads();
    if (tid < 8) {
        float a = 0.f;
#pragma unroll
        for (int f = 0; f < 32; f++) a += msm[f] * sew1[tid * 32 + f];
        t8m[tid] = fmaxf(a, 0.f);
    }
    __syncthreads();
    if (tid < 32) {
        float a = 0.f;
#pragma unroll
        for (int k = 0; k < 8; k++) a += t8m[k] * sew2[tid * 8 + k];
        gate[tid] = 1.f / (1.f + __expf(-a));
    }
    {
        const float* hp = g_h2 + (b * NC + tid) * 32;
#pragma unroll
        for (int f = 0; f < 32; f++) rows[tid * 33 + f] = hp[f];
    }
    __syncthreads();
    if (tid < 32) {
        float s = 0.f;
        for (int c = 0; c < NC; c++) s += rows[c * 33 + tid];
        pooled[tid] = s * (1.f / (float)NC) * gate[tid];
    }
    __syncthreads();
    if (tid < 2) {
        float a = clfb[tid];
#pragma unroll
        for (int f = 0; f < 32; f++) a += pooled[f] * clfw[tid * 32 + f];
        out[b * 2 + tid] = a;
    }
}

// ---------------------------------------------------------------------------
// Launch
// ---------------------------------------------------------------------------
extern "C" void kernel_launch(void* const* d_in, const int* in_sizes, int n_in,
                              void* d_out, int out_size) {
    const float* x      = (const float*)d_in[0];
    const int*   eidx   = (const int*)  d_in[1];
    const float* c1w    = (const float*)d_in[2];
    const float* bn_c1  = (const float*)d_in[3];
    const float* dw_w   = (const float*)d_in[4];
    const float* bn_c2  = (const float*)d_in[5];
    const float* sdw_w  = (const float*)d_in[6];
    const float* spw_w  = (const float*)d_in[7];
    const float* bn_c3  = (const float*)d_in[8];
    const float* embed  = (const float*)d_in[9];
    const float* g1_w   = (const float*)d_in[10];
    const float* g1_as  = (const float*)d_in[11];
    const float* g1_ad  = (const float*)d_in[12];
    const float* g1_b   = (const float*)d_in[13];
    const float* bn_g1  = (const float*)d_in[14];
    const float* skip1  = (const float*)d_in[15];
    const float* se1w1  = (const float*)d_in[16];
    const float* se1w2  = (const float*)d_in[17];
    const float* g2_w   = (const float*)d_in[18];
    const float* g2_as  = (const float*)d_in[19];
    const float* g2_ad  = (const float*)d_in[20];
    const float* g2_b   = (const float*)d_in[21];
    const float* bn_g2  = (const float*)d_in[22];
    const float* se2w1  = (const float*)d_in[23];
    const float* se2w2  = (const float*)d_in[24];
    const float* clf_w  = (const float*)d_in[25];
    const float* clf_b  = (const float*)d_in[26];
    float* out = (float*)d_out;

    cudaFuncSetAttribute(feat_kernel, cudaFuncAttributeMaxDynamicSharedMemorySize,
                         FEAT_SMEM_BYTES);

    feat_kernel<<<NROWS, 256, FEAT_SMEM_BYTES>>>(x, c1w, bn_c1, dw_w, bn_c2,
                                                 sdw_w, spw_w, bn_c3);
    graph_kernel<<<1, 256>>>(embed, eidx);

    gat_head_kernel<16, 1><<<NB * NH, 256>>>(g1_w, g1_as, g1_ad, nullptr, nullptr);
    gat_epi_kernel<1><<<NROWS / 8, 256>>>(g1_b, bn_g1, skip1, nullptr, nullptr);

    gat_head_kernel<32, 2><<<NB * NH, 256>>>(g2_w, g2_as, g2_ad, se1w1, se1w2);
    gat_epi_kernel<2><<<NROWS / 8, 256>>>(g2_b, bn_g2, nullptr, se1w1, se1w2);

    final_kernel<<<NB, 64>>>(se2w1, se2w2, clf_w, clf_b, out);
}

// round 5
// speedup vs baseline: 1.0905x; 1.0001x over previous
#include <cuda_runtime.h>
#include <cuda_fp16.h>
#include <math.h>

// ---------------------------------------------------------------------------
// Problem constants
// ---------------------------------------------------------------------------
#define NB   128
#define NC   64
#define NT   500
#define NF   16
#define NGC  32
#define NH   4
#define NROWS (NB*NC)   // 8192

// ---------------------------------------------------------------------------
// Device scratch
// ---------------------------------------------------------------------------
__device__ float g_feats[NROWS * NF];
__device__ float g_M[NC * NC];
__device__ float g_h1[NROWS * NGC];
__device__ float g_h2[NROWS * NGC];
__device__ float g_sum1[NGC];
__device__ float g_sum2[NGC];
__device__ float g_headout[NB * NH * NC * NGC];   // [b][h][i][f]  4MB

// ---------------------------------------------------------------------------
// f32x2 packed helpers
// ---------------------------------------------------------------------------
__device__ __forceinline__ unsigned long long pk2(float a, float b) {
    unsigned long long r;
    asm("mov.b64 %0, {%1, %2};" : "=l"(r) : "f"(a), "f"(b));
    return r;
}
__device__ __forceinline__ void upk2(unsigned long long v, float& a, float& b) {
    asm("mov.b64 {%0, %1}, %2;" : "=f"(a), "=f"(b) : "l"(v));
}
__device__ __forceinline__ void fma2(unsigned long long& d, unsigned long long a,
                                     unsigned long long b) {
    asm("fma.rn.f32x2 %0, %1, %2, %0;" : "+l"(d) : "l"(a), "l"(b));
}
__device__ __forceinline__ float eluf(float x) {
    return x > 0.f ? x : (__expf(x) - 1.f);
}

// ---------------------------------------------------------------------------
// Kernel A: fused feature extractor.  One block per (b,c) sequence.
// Redesigned for occupancy: k-outer conv1 (acc regs instead of window regs),
// fp16 stage-2 buffer.  smem 57152B -> 4 CTAs/SM;  regs capped at 64.
// byte layout:
//   0      xs      560 f
//   2240   s1      8064 f          (16 rows x 504, data at [1..500])
//   34496  s2h     8064 half
//   50624  w1dup   800 f  (400 float2)
//   53824  spwdup  512 f  (256 float2)
//   55872  dws     48 f
//   56064  sdws    48 f
//   56256  bn      96 f   (sc1,sh1,sc2,sh2,sc3,sh3)
//   56640  red     128 f
// ---------------------------------------------------------------------------
#define FEAT_SMEM_BYTES 57152

__global__ __launch_bounds__(256, 4)
void feat_kernel(const float* __restrict__ x,
                 const float* __restrict__ c1w,
                 const float* __restrict__ bn1,
                 const float* __restrict__ dwwg,
                 const float* __restrict__ bn2,
                 const float* __restrict__ sdwg,
                 const float* __restrict__ spwg,
                 const float* __restrict__ bn3) {
    extern __shared__ char smraw[];
    float*  xs     = (float*)(smraw);
    float*  s1     = (float*)(smraw + 2240);
    __half* s2h    = (__half*)(smraw + 34496);
    float*  w1dup  = (float*)(smraw + 50624);
    float*  spwdup = (float*)(smraw + 53824);
    float*  dws    = (float*)(smraw + 55872);
    float*  sdws   = (float*)(smraw + 56064);
    float*  sc1    = (float*)(smraw + 56256);
    float*  sh1 = sc1 + 16; float* sc2 = sc1 + 32; float* sh2 = sc1 + 48;
    float*  sc3 = sc1 + 64; float* sh3 = sc1 + 80;
    float*  red    = (float*)(smraw + 56640);

    const int tid = threadIdx.x;
    const int seq = blockIdx.x;

    {
        const float* xr = x + seq * NT;
        for (int i = tid; i < 560; i += 256) {
            float v = 0.f;
            if (i >= 12 && i < 512) v = xr[i - 12];
            xs[i] = v;
        }
        if (tid < 400) {
            float w = c1w[tid];
            ((float2*)w1dup)[tid] = make_float2(w, w);
        }
        {
            float w = spwg[tid];
            ((float2*)spwdup)[tid] = make_float2(w, w);
        }
        if (tid < 48) { dws[tid] = dwwg[tid]; sdws[tid] = sdwg[tid]; }
        if (tid < 16) {
            float s = bn1[tid] * rsqrtf(bn1[48 + tid] + 1e-5f);
            sc1[tid] = s; sh1[tid] = bn1[16 + tid] - bn1[32 + tid] * s;
            s = bn2[tid] * rsqrtf(bn2[48 + tid] + 1e-5f);
            sc2[tid] = s; sh2[tid] = bn2[16 + tid] - bn2[32 + tid] * s;
            s = bn3[tid] * rsqrtf(bn3[48 + tid] + 1e-5f);
            sc3[tid] = s; sh3[tid] = bn3[16 + tid] - bn3[32 + tid] * s;
        }
    }
    __syncthreads();

    const int t0 = tid;
    const int t1 = tid + 256;
    const bool v1 = (t1 < NT);

    // --- stage 1: conv1 (K=25) + BN + ELU, k-outer with packed accumulators
    {
        unsigned long long acc1[16];
#pragma unroll
        for (int c = 0; c < 16; c++) acc1[c] = 0ull;
        const unsigned long long* w1q = (const unsigned long long*)w1dup;
#pragma unroll 5
        for (int k = 0; k < 25; k++) {
            const unsigned long long xv = pk2(xs[t0 + k], xs[t1 + k]);
#pragma unroll
            for (int c = 0; c < 16; c++) fma2(acc1[c], xv, w1q[c * 25 + k]);
        }
#pragma unroll
        for (int c = 0; c < 16; c++) {
            float a0, a1; upk2(acc1[c], a0, a1);
            const float sc = sc1[c], sh = sh1[c];
            float* row = s1 + c * 504;
            row[1 + t0] = eluf(fmaf(a0, sc, sh));
            if (v1) row[1 + t1] = eluf(fmaf(a1, sc, sh));
        }
        if (tid < 16) { s1[tid * 504] = 0.f; s1[tid * 504 + 501] = 0.f; }
    }
    __syncthreads();

    // --- stage 2: depthwise conv (K=3) + BN + ELU -> fp16 buffer
#pragma unroll
    for (int c = 0; c < 16; c++) {
        const float* r = s1 + c * 504;
        const float w0 = dws[c * 3], wA = dws[c * 3 + 1], w2 = dws[c * 3 + 2];
        const float sc = sc2[c], sh = sh2[c];
        float v0 = w0 * r[t0] + wA * r[t0 + 1] + w2 * r[t0 + 2];
        s2h[c * 504 + 1 + t0] = __float2half(eluf(fmaf(v0, sc, sh)));
        if (v1) {
            float u = w0 * r[t1] + wA * r[t1 + 1] + w2 * r[t1 + 2];
            s2h[c * 504 + 1 + t1] = __float2half(eluf(fmaf(u, sc, sh)));
        }
    }
    if (tid < 16) {
        s2h[tid * 504] = __float2half(0.f);
        s2h[tid * 504 + 501] = __float2half(0.f);
    }
    __syncthreads();

    // --- stage 3: sdw (K=3) -> pointwise 16x16 (packed) -> BN+ELU -> mean
    float means[16];
    {
        const int t1r = v1 ? t1 : 0;
        unsigned long long tmp[16];
#pragma unroll
        for (int c = 0; c < 16; c++) {
            const __half* r = s2h + c * 504;
            const float w0 = sdws[c * 3], wA = sdws[c * 3 + 1], w2 = sdws[c * 3 + 2];
            float a0 = w0 * __half2float(r[t0]) + wA * __half2float(r[t0 + 1]) +
                       w2 * __half2float(r[t0 + 2]);
            float a1 = w0 * __half2float(r[t1r]) + wA * __half2float(r[t1r + 1]) +
                       w2 * __half2float(r[t1r + 2]);
            tmp[c] = pk2(a0, a1);
        }
        const unsigned long long* spq = (const unsigned long long*)spwdup;
#pragma unroll
        for (int f = 0; f < 16; f++) {
            unsigned long long a = 0ull;
#pragma unroll
            for (int c = 0; c < 16; c++) fma2(a, tmp[c], spq[f * 16 + c]);
            float a0, a1; upk2(a, a0, a1);
            const float sc = sc3[f], sh = sh3[f];
            float e0 = eluf(fmaf(a0, sc, sh));
            float e1 = eluf(fmaf(a1, sc, sh));
            means[f] = e0 + (v1 ? e1 : 0.f);
        }
    }

    {
        const int lane = tid & 31, wid = tid >> 5;
#pragma unroll
        for (int f = 0; f < 16; f++) {
            float v = means[f];
            for (int o = 16; o; o >>= 1) v += __shfl_down_sync(0xffffffffu, v, o);
            if (lane == 0) red[wid * 16 + f] = v;
        }
        __syncthreads();
        if (tid < 16) {
            float s = 0.f;
            for (int w = 0; w < 8; w++) s += red[w * 16 + tid];
            g_feats[seq * 16 + tid] = s * (1.f / (float)NT);
        }
    }
}

// ---------------------------------------------------------------------------
// Kernel B: build multiplicity matrix M, zero SE accumulators.  One block.
// ---------------------------------------------------------------------------
__global__ void graph_kernel(const float* __restrict__ emb,
                             const int* __restrict__ eidx) {
    __shared__ float E[NC * NF];
    __shared__ float As[NC * 65];
    __shared__ float rs[NC];
    __shared__ float Ms[NC * NC];
    const int tid = threadIdx.x;

    for (int i = tid; i < NC * NF; i += 256) E[i] = emb[i];
    for (int i = tid; i < NC * NC; i += 256) Ms[i] = 0.f;
    if (tid < NGC) { g_sum1[tid] = 0.f; g_sum2[tid] = 0.f; }
    __syncthreads();

    for (int idx = tid; idx < NC * NC; idx += 256) {
        const int i = idx >> 6, j = idx & 63;
        float a = 0.f;
#pragma unroll
        for (int f = 0; f < NF; f++) a += E[i * NF + f] * E[j * NF + f];
        As[i * 65 + j] = fmaxf(a, 0.f);
    }
    __syncthreads();
    if (tid < NC) {
        float s = 0.f;
        for (int j = 0; j < NC; j++) s += As[tid * 65 + j];
        rs[tid] = s + 1e-6f;
    }
    __syncthreads();
    if (tid < 256) {
        const int s = eidx[tid], d = eidx[256 + tid];
        atomicAdd(&Ms[s * NC + d], 1.f);
    }
    __syncthreads();
    for (int idx = tid; idx < NC * NC; idx += 256) {
        const int i = idx >> 6, j = idx & 63;
        const float dyn = (As[i * 65 + j] / rs[i] > 0.1f) ? 1.f : 0.f;
        g_M[idx] = (i == j) ? 1.f : (Ms[idx] + dyn);
    }
}

// ---------------------------------------------------------------------------
// Kernel C: per-(batch,head) GAT attention.  512 blocks -> real occupancy.
// Writes per-head results to g_headout[b][h][i][f].
// ---------------------------------------------------------------------------
template <int INF, int LAYER>
__global__ __launch_bounds__(256)
void gat_head_kernel(const float* __restrict__ W,
                     const float* __restrict__ asrc,
                     const float* __restrict__ adst,
                     const float* __restrict__ sew1,
                     const float* __restrict__ sew2) {
    __shared__ float Xs[NC * (INF + 1)];
    __shared__ float Wh[INF * 33];
    __shared__ float xl[NC * 33];
    __shared__ float ss[NC];
    __shared__ float dd[NC];
    __shared__ float Ms[NC * 65];
    __shared__ float gate[32], msm[32], t8m[8];

    const int tid = threadIdx.x;
    const int h = blockIdx.x & 3;
    const int b = blockIdx.x >> 2;
    const float* Xin = (LAYER == 1) ? g_feats : g_h1;

    if (LAYER == 2) {
        if (tid < 32) msm[tid] = g_sum1[tid] * (1.f / (float)NROWS);
        __syncthreads();
        if (tid < 8) {
            float a = 0.f;
#pragma unroll
            for (int f = 0; f < 32; f++) a += msm[f] * sew1[tid * 32 + f];
            t8m[tid] = fmaxf(a, 0.f);
        }
        __syncthreads();
        if (tid < 32) {
            float a = 0.f;
#pragma unroll
            for (int k = 0; k < 8; k++) a += t8m[k] * sew2[tid * 8 + k];
            gate[tid] = 1.f / (1.f + __expf(-a));
        }
        __syncthreads();
    }

    for (int i = tid; i < NC * NC; i += 256)
        Ms[(i >> 6) * 65 + (i & 63)] = g_M[i];
    for (int i = tid; i < INF * 32; i += 256) {
        const int in = i >> 5, f = i & 31;
        Wh[in * 33 + f] = W[in * 128 + h * 32 + f];
    }
    for (int i = tid; i < NC * INF; i += 256) {
        const int r = i / INF, f = i - r * INF;
        float v = Xin[(b * NC + r) * INF + f];
        if (LAYER == 2) v *= gate[f];
        Xs[r * (INF + 1) + f] = v;
    }
    __syncthreads();

    // xl[j][f] = sum_in Xs[j][in] * Wh[in][f]
    for (int idx = tid; idx < NC * 32; idx += 256) {
        const int j = idx >> 5, f = idx & 31;
        float a = 0.f;
#pragma unroll
        for (int in = 0; in < INF; in++)
            a = fmaf(Xs[j * (INF + 1) + in], Wh[in * 33 + f], a);
        xl[j * 33 + f] = a;
    }
    __syncthreads();

    if (tid < 128) {
        const int node = tid & 63, which = tid >> 6;
        const float* av = which ? adst : asrc;
        float a = 0.f;
#pragma unroll
        for (int f = 0; f < 32; f++)
            a = fmaf(xl[node * 33 + f], av[h * 32 + f], a);
        if (which) dd[node] = a; else ss[node] = a;
    }
    __syncthreads();

    // attention: thread = (i, q); q covers 8 features
    const int i = tid >> 2, q = tid & 3;
    const float di = dd[i];
    float mx = -1e30f;
    for (int j = 0; j < NC; j++) {
        const float Mij = Ms[i * 65 + j];
        float e = di + ss[j];
        e = (e >= 0.f) ? e : 0.2f * e;
        mx = (Mij > 0.f) ? fmaxf(mx, e) : mx;
    }
    float Z = 0.f;
    float acc[8];
#pragma unroll
    for (int f = 0; f < 8; f++) acc[f] = 0.f;
    const float* xr = xl + q * 8;
    for (int j = 0; j < NC; j++) {
        const float Mij = Ms[i * 65 + j];
        float e = di + ss[j];
        e = (e >= 0.f) ? e : 0.2f * e;
        const float w = Mij * __expf(e - mx);
        Z += w;
        const float* row = xr + j * 33;
#pragma unroll
        for (int f = 0; f < 8; f++) acc[f] = fmaf(w, row[f], acc[f]);
    }
    const float invZ = 1.f / Z;
    float* outp = g_headout + ((b * 4 + h) * NC + i) * 32 + q * 8;
#pragma unroll
    for (int f = 0; f < 8; f++) outp[f] = acc[f] * invZ;
}

// ---------------------------------------------------------------------------
// Kernel D: GAT epilogue: head mean + bias + BN + skip/residual + GELU,
// write h, accumulate SE sums.  1024 blocks x 256 thr (8 rows x 32 f each).
// ---------------------------------------------------------------------------
template <int LAYER>
__global__ __launch_bounds__(256)
void gat_epi_kernel(const float* __restrict__ bias,
                    const float* __restrict__ bnp,
                    const float* __restrict__ skipw,
                    const float* __restrict__ sew1,
                    const float* __restrict__ sew2) {
    __shared__ float bnsc[32], bnsh[32], bs[32];
    __shared__ float sk[512];               // layer1: skipw transposed [in][f]
    __shared__ float gate[32], msm[32], t8m[8];
    __shared__ float red[8 * 32];

    const int tid = threadIdx.x;
    if (tid < 32) {
        const float s = bnp[tid] * rsqrtf(bnp[96 + tid] + 1e-5f);
        bnsc[tid] = s; bnsh[tid] = bnp[32 + tid] - bnp[64 + tid] * s;
        bs[tid] = bias[tid];
    }
    if (LAYER == 1) {
        for (int i = tid; i < 512; i += 256)
            sk[i] = skipw[(i & 31) * 16 + (i >> 5)];   // sk[in*32+f]
    } else {
        if (tid < 32) msm[tid] = g_sum1[tid] * (1.f / (float)NROWS);
        __syncthreads();
        if (tid < 8) {
            float a = 0.f;
#pragma unroll
            for (int f = 0; f < 32; f++) a += msm[f] * sew1[tid * 32 + f];
            t8m[tid] = fmaxf(a, 0.f);
        }
        __syncthreads();
        if (tid < 32) {
            float a = 0.f;
#pragma unroll
            for (int k = 0; k < 8; k++) a += t8m[k] * sew2[tid * 8 + k];
            gate[tid] = 1.f / (1.f + __expf(-a));
        }
    }
    __syncthreads();

    const int w = tid >> 5, f = tid & 31;
    const int row = blockIdx.x * 8 + w;
    const int b = row >> 6, i = row & 63;

    float o = 0.f;
#pragma unroll
    for (int h = 0; h < 4; h++)
        o += g_headout[((b * 4 + h) * NC + i) * 32 + f];
    o = o * 0.25f + bs[f];
    o = fmaf(o, bnsc[f], bnsh[f]);

    float res;
    if (LAYER == 1) {
        const float* xr = g_feats + row * 16;
        res = 0.f;
#pragma unroll
        for (int in = 0; in < 16; in++)
            res = fmaf(__ldg(xr + in), sk[in * 32 + f], res);
    } else {
        res = gate[f] * g_h1[row * 32 + f];
    }
    o += res;
    const float gl = 0.5f * o * (1.f + erff(o * 0.70710678118f));
    ((LAYER == 1) ? g_h1 : g_h2)[row * 32 + f] = gl;

    red[w * 32 + f] = gl;
    __syncthreads();
    if (tid < 32) {
        float s = 0.f;
#pragma unroll
        for (int r = 0; r < 8; r++) s += red[r * 32 + tid];
        atomicAdd((LAYER == 1) ? &g_sum1[tid] : &g_sum2[tid], s);
    }
}

// ---------------------------------------------------------------------------
// Kernel E: SE2 gate + node mean-pool + classifier.  One block per batch.
// ---------------------------------------------------------------------------
__global__ void final_kernel(const float* __restrict__ sew1,
                             const float* __restrict__ sew2,
                             const float* __restrict__ clfw,
                             const float* __restrict__ clfb,
                             float* __restrict__ out) {
    __shared__ float rows[NC * 33];
    __shared__ float msm[32], t8m[8], gate[32], pooled[32];
    const int tid = threadIdx.x;
    const int b   = blockIdx.x;

    if (tid < 32) msm[tid] = g_sum2[tid] * (1.f / (float)NROWS);
    __syncthreads();
    if (tid < 8) {
        float a = 0.f;
#pragma unroll
        for (int f = 0; f < 32; f++) a += msm[f] * sew1[tid * 32 + f];
        t8m[tid] = fmaxf(a, 0.f);
    }
    __syncthreads();
    if (tid < 32) {
        float a = 0.f;
#pragma unroll
        for (int k = 0; k < 8; k++) a += t8m[k] * sew2[tid * 8 + k];
        gate[tid] = 1.f / (1.f + __expf(-a));
    }
    {
        const float* hp = g_h2 + (b * NC + tid) * 32;
#pragma unroll
        for (int f = 0; f < 32; f++) rows[tid * 33 + f] = hp[f];
    }
    __syncthreads();
    if (tid < 32) {
        float s = 0.f;
        for (int c = 0; c < NC; c++) s += rows[c * 33 + tid];
        pooled[tid] = s * (1.f / (float)NC) * gate[tid];
    }
    __syncthreads();
    if (tid < 2) {
        float a = clfb[tid];
#pragma unroll
        for (int f = 0; f < 32; f++) a += pooled[f] * clfw[tid * 32 + f];
        out[b * 2 + tid] = a;
    }
}

// ---------------------------------------------------------------------------
// Launch
// ---------------------------------------------------------------------------
extern "C" void kernel_launch(void* const* d_in, const int* in_sizes, int n_in,
                              void* d_out, int out_size) {
    const float* x      = (const float*)d_in[0];
    const int*   eidx   = (const int*)  d_in[1];
    const float* c1w    = (const float*)d_in[2];
    const float* bn_c1  = (const float*)d_in[3];
    const float* dw_w   = (const float*)d_in[4];
    const float* bn_c2  = (const float*)d_in[5];
    const float* sdw_w  = (const float*)d_in[6];
    const float* spw_w  = (const float*)d_in[7];
    const float* bn_c3  = (const float*)d_in[8];
    const float* embed  = (const float*)d_in[9];
    const float* g1_w   = (const float*)d_in[10];
    const float* g1_as  = (const float*)d_in[11];
    const float* g1_ad  = (const float*)d_in[12];
    const float* g1_b   = (const float*)d_in[13];
    const float* bn_g1  = (const float*)d_in[14];
    const float* skip1  = (const float*)d_in[15];
    const float* se1w1  = (const float*)d_in[16];
    const float* se1w2  = (const float*)d_in[17];
    const float* g2_w   = (const float*)d_in[18];
    const float* g2_as  = (const float*)d_in[19];
    const float* g2_ad  = (const float*)d_in[20];
    const float* g2_b   = (const float*)d_in[21];
    const float* bn_g2  = (const float*)d_in[22];
    const float* se2w1  = (const float*)d_in[23];
    const float* se2w2  = (const float*)d_in[24];
    const float* clf_w  = (const float*)d_in[25];
    const float* clf_b  = (const float*)d_in[26];
    float* out = (float*)d_out;

    cudaFuncSetAttribute(feat_kernel, cudaFuncAttributeMaxDynamicSharedMemorySize,
                         FEAT_SMEM_BYTES);

    feat_kernel<<<NROWS, 256, FEAT_SMEM_BYTES>>>(x, c1w, bn_c1, dw_w, bn_c2,
                                                 sdw_w, spw_w, bn_c3);
    graph_kernel<<<1, 256>>>(embed, eidx);

    gat_head_kernel<16, 1><<<NB * NH, 256>>>(g1_w, g1_as, g1_ad, nullptr, nullptr);
    gat_epi_kernel<1><<<NROWS / 8, 256>>>(g1_b, bn_g1, skip1, nullptr, nullptr);

    gat_head_kernel<32, 2><<<NB * NH, 256>>>(g2_w, g2_as, g2_ad, se1w1, se1w2);
    gat_epi_kernel<2><<<NROWS / 8, 256>>>(g2_b, bn_g2, nullptr, se1w1, se1w2);

    final_kernel<<<NB, 64>>>(se2w1, se2w2, clf_w, clf_b, out);
}